// round 1
// baseline (speedup 1.0000x reference)
#include <cuda_runtime.h>

#define NB   32     // batch
#define SEQL 256    // L
#define NH   128    // hidden
#define NVOC 10
#define NDIG 128    // digits = L/2
#define NT   129    // digits + 1
#define TP   144    // padded time row: [0,4) zero halo, [4,133) data, [133,144) zero halo
#define HALO 4
#define NITER 131   // digits + 3
#define NG   4      // channel groups (CTAs) per batch
#define OC   32     // output channels per CTA
#define NTHREADS 256

// Double-buffered hidden state, halos stay zero forever.
__device__ float g_h[2][NB][NH][TP];

// ---------- packed f32x2 helpers (Blackwell dual-rate fp32) ----------
__device__ __forceinline__ unsigned long long pk2(float a, float b){
    unsigned long long r;
    asm("mov.b64 %0, {%1, %2};" : "=l"(r) : "f"(a), "f"(b));
    return r;
}
__device__ __forceinline__ void fma2(unsigned long long& d, unsigned long long a, unsigned long long b){
    asm("fma.rn.f32x2 %0, %1, %2, %0;" : "+l"(d) : "l"(a), "l"(b));
}
__device__ __forceinline__ void unpk2(unsigned long long v, float& a, float& b){
    asm("mov.b64 {%0, %1}, %2;" : "=f"(a), "=f"(b) : "l"(v));
}

#define CLUSTER_SYNC() do { \
    asm volatile("barrier.cluster.arrive.aligned;" ::: "memory"); \
    asm volatile("barrier.cluster.wait.aligned;"   ::: "memory"); } while(0)

// One residual dilated-conv iteration for this CTA's 32 output channels.
// src/dst point at g_h[buf][b][0][0]. hs = smem staging of all 128 channels.
// ws layout: ws[(c*3+k)*OC + ol]  (8 float4 per (c,k), og-indexed)
template<int D>
__device__ __forceinline__ void conv_iter(
    const float* __restrict__ src, float* __restrict__ dst,
    float* __restrict__ hs, const float* __restrict__ ws,
    const float* __restrict__ cb, int obase)
{
    const int tid = threadIdx.x;

    // Stage full h[b] from L2 (bypass L1: peers wrote it last iteration).
    {
        const float4* s4 = (const float4*)src;
        float4*       d4 = (float4*)hs;
        #pragma unroll
        for (int i = tid; i < NH*TP/4; i += NTHREADS) d4[i] = __ldcg(s4 + i);
    }
    __syncthreads();

    const int  og   = tid & 7;          // 8 o-groups x 4 channels
    const int  tt   = tid >> 3;         // 32 t-tiles x 4 positions
    const int  t0   = tt * 4;           // covers t = 0..127
    const bool xtra = (tt == 31);       // these lanes also compute t = 128

    unsigned long long acc[4][2];
    float accx[4];
    #pragma unroll
    for (int o = 0; o < 4; o++){ acc[o][0] = 0ull; acc[o][1] = 0ull; accx[o] = 0.f; }

    // s[j] = h[c][t0 - 4 + j], j = 0..11; span covers taps for D in {1,2,4}
    const float*  hrow = hs + t0;                    // hs[c*TP + HALO + t0 - 4]
    const float4* wp   = (const float4*)ws + og;     // advances 24 float4 per c

    #pragma unroll 2
    for (int c = 0; c < NH; c++){
        float4 q0 = ((const float4*)hrow)[0];
        float4 q1 = ((const float4*)hrow)[1];
        float4 q2 = ((const float4*)hrow)[2];
        float s[12] = {q0.x,q0.y,q0.z,q0.w, q1.x,q1.y,q1.z,q1.w, q2.x,q2.y,q2.z,q2.w};

        float s12 = 0.f;
        if (D == 4) { if (xtra) s12 = hrow[12]; }

        unsigned long long hm0 = pk2(s[4-D], s[5-D]);
        unsigned long long hm1 = pk2(s[6-D], s[7-D]);
        unsigned long long hz0 = pk2(s[4],   s[5]);
        unsigned long long hz1 = pk2(s[6],   s[7]);
        unsigned long long hp0 = pk2(s[4+D], s[5+D]);
        unsigned long long hp1 = pk2(s[6+D], s[7+D]);
        const float xm = s[8-D];
        const float xz = s[8];
        const float xp = (D == 4) ? s12 : s[8+D];

        float4 w0 = wp[0];      // k = 0 (tap t-D)
        float4 w1 = wp[8];      // k = 1 (tap t)
        float4 w2 = wp[16];     // k = 2 (tap t+D)

        #define DO_O(oi, W0, W1, W2) do { \
            unsigned long long d0 = pk2((W0), (W0)); \
            unsigned long long d1 = pk2((W1), (W1)); \
            unsigned long long d2 = pk2((W2), (W2)); \
            fma2(acc[oi][0], d0, hm0); fma2(acc[oi][1], d0, hm1); \
            fma2(acc[oi][0], d1, hz0); fma2(acc[oi][1], d1, hz1); \
            fma2(acc[oi][0], d2, hp0); fma2(acc[oi][1], d2, hp1); \
            if (xtra) accx[oi] = fmaf((W0), xm, fmaf((W1), xz, fmaf((W2), xp, accx[oi]))); \
        } while(0)

        DO_O(0, w0.x, w1.x, w2.x);
        DO_O(1, w0.y, w1.y, w2.y);
        DO_O(2, w0.z, w1.z, w2.z);
        DO_O(3, w0.w, w1.w, w2.w);
        #undef DO_O

        hrow += TP;
        wp   += 24;
    }

    // Epilogue: bias + relu + residual, write own slice to dst (L2).
    #pragma unroll
    for (int o = 0; o < 4; o++){
        const int   ol   = og*4 + o;
        const int   cg   = obase + ol;
        float r0, r1, r2, r3;
        unpk2(acc[o][0], r0, r1);
        unpk2(acc[o][1], r2, r3);
        const float bias = cb[ol];
        const float* hold = hs + cg*TP + HALO + t0;
        float*       drow = dst + cg*TP + HALO + t0;
        float4 v;
        v.x = fmaxf(r0 + bias, 0.f) + hold[0];
        v.y = fmaxf(r1 + bias, 0.f) + hold[1];
        v.z = fmaxf(r2 + bias, 0.f) + hold[2];
        v.w = fmaxf(r3 + bias, 0.f) + hold[3];
        __stcg((float4*)drow, v);
        if (xtra) __stcg(drow + 4, fmaxf(accx[o] + bias, 0.f) + hold[4]);
    }
}

__global__ void __cluster_dims__(NG, 1, 1) __launch_bounds__(NTHREADS, 1)
vgt_kernel(const int* __restrict__ x, const float* __restrict__ emb_w,
           const float* __restrict__ red_w, const float* __restrict__ red_b,
           const float* __restrict__ conv_w, const float* __restrict__ conv_b,
           const float* __restrict__ out_w, const float* __restrict__ out_b,
           float* __restrict__ out)
{
    extern __shared__ float sm[];
    float* hs = sm;                       // NH*TP          = 18432 floats
    float* ws = hs + NH*TP;               // NH*3*OC        = 12288 floats
    float* m1 = ws + NH*3*OC;             // NVOC*OC        = 320
    float* m2 = m1 + NVOC*OC;             // NVOC*OC        = 320
    float* cb = m2 + NVOC*OC;             // OC             = 32

    const int tid   = threadIdx.x;
    const int b     = blockIdx.x >> 2;
    const int g     = blockIdx.x & 3;
    const int obase = g * OC;

    // ---- prologue phase 1: weights, fused reducer tables, zero state ----
    for (int idx = tid; idx < NH*3*OC; idx += NTHREADS){
        int ol = idx & 31;
        int ck = idx >> 5;          // = c*3 + k
        int k  = ck % 3;
        int c  = ck / 3;
        ws[idx] = conv_w[((obase + ol)*NH + c)*3 + k];
    }
    if (tid < OC) cb[tid] = conv_b[obase + tid];

    // M1[v][o] = sum_c red_w[o,c]*emb[v,c]; M2 uses red_w[o,128+c]
    for (int idx = tid; idx < NVOC*OC; idx += NTHREADS){
        int v  = idx / OC;
        int ol = idx % OC;
        const float* rw = red_w + (obase + ol)*(2*NH);
        const float* ew = emb_w + v*NH;
        float s1 = 0.f, s2 = 0.f;
        for (int c = 0; c < NH; c++){
            float e = ew[c];
            s1 = fmaf(rw[c],      e, s1);
            s2 = fmaf(rw[NH + c], e, s2);
        }
        m1[idx] = s1;
        m2[idx] = s2;
    }

    // zero both buffers of my (b, channel-slice) — establishes halos
    for (int idx = tid; idx < 2*OC*TP; idx += NTHREADS){
        int bb = idx / (OC*TP);
        int r  = idx - bb*(OC*TP);
        int c  = r / TP;
        int t  = r - c*TP;
        g_h[bb][b][obase + c][t] = 0.f;
    }
    __syncthreads();

    // ---- prologue phase 2: h0 = relu(M1[x[t]] + M2[x[t+128]] + red_b) ----
    {
        const int*   xb  = x + b*SEQL;
        const float* rbp = red_b + obase;
        for (int idx = tid; idx < OC*NDIG; idx += NTHREADS){
            int ol = idx >> 7;
            int t  = idx & 127;
            int v1 = xb[t];
            int v2 = xb[t + NDIG];
            float val = m1[v1*OC + ol] + m2[v2*OC + ol] + rbp[ol];
            g_h[0][b][obase + ol][HALO + t] = fmaxf(val, 0.f);
        }
    }
    __threadfence();
    CLUSTER_SYNC();

    // ---- 131 residual conv iterations (cluster-synced, double-buffered) ----
    int cur = 0;
    #pragma unroll 1
    for (int i = 0; i < 4; i++){
        conv_iter<1>(&g_h[cur][b][0][0], &g_h[cur ^ 1][b][0][0], hs, ws, cb, obase);
        __threadfence(); CLUSTER_SYNC();
        cur ^= 1;
    }
    #pragma unroll 1
    for (int i = 0; i < 4; i++){
        conv_iter<2>(&g_h[cur][b][0][0], &g_h[cur ^ 1][b][0][0], hs, ws, cb, obase);
        __threadfence(); CLUSTER_SYNC();
        cur ^= 1;
    }
    #pragma unroll 1
    for (int i = 0; i < NITER - 8; i++){
        conv_iter<4>(&g_h[cur][b][0][0], &g_h[cur ^ 1][b][0][0], hs, ws, cb, obase);
        __threadfence(); CLUSTER_SYNC();
        cur ^= 1;
    }

    // ---- output head: out[b,t,o] = sum_c out_w[o,c]*h[b,c,t] + out_b[o] ----
    {
        const float4* s4 = (const float4*)&g_h[cur][b][0][0];
        float4*       d4 = (float4*)hs;
        #pragma unroll
        for (int i = tid; i < NH*TP/4; i += NTHREADS) d4[i] = __ldcg(s4 + i);
    }
    __syncthreads();

    const int tstart = g * 33;
    const int tcnt   = (NT - tstart) < 33 ? (NT - tstart) : 33;   // g=3 -> 30
    for (int idx = tid; idx < tcnt*NVOC; idx += NTHREADS){
        int t = tstart + idx / NVOC;
        int o = idx % NVOC;
        const float* wrow = out_w + o*NH;
        float s = out_b[o];
        #pragma unroll 8
        for (int c = 0; c < NH; c++)
            s = fmaf(wrow[c], hs[c*TP + HALO + t], s);
        out[(b*NT + t)*NVOC + o] = s;
    }
}

extern "C" void kernel_launch(void* const* d_in, const int* in_sizes, int n_in,
                              void* d_out, int out_size)
{
    (void)in_sizes; (void)n_in; (void)out_size;
    const int*   x      = (const int*)  d_in[0];
    const float* emb_w  = (const float*)d_in[1];
    const float* red_w  = (const float*)d_in[2];
    const float* red_b  = (const float*)d_in[3];
    const float* conv_w = (const float*)d_in[4];
    const float* conv_b = (const float*)d_in[5];
    const float* out_w  = (const float*)d_in[6];
    const float* out_b  = (const float*)d_in[7];
    float* out = (float*)d_out;

    const size_t smem = (size_t)(NH*TP + NH*3*OC + 2*NVOC*OC + OC) * sizeof(float); // ~125.6 KB
    cudaFuncSetAttribute(vgt_kernel, cudaFuncAttributeMaxDynamicSharedMemorySize, (int)smem);
    vgt_kernel<<<NB*NG, NTHREADS, smem>>>(x, emb_w, red_w, red_b,
                                          conv_w, conv_b, out_w, out_b, out);
}